// round 14
// baseline (speedup 1.0000x reference)
#include <cuda_runtime.h>
#include <math.h>

#define RESN   320
#define MTRAJ  25600
#define NB     16
#define OSN    400
#define GL     8
#define LSTR   12   /* lane-stride in floats: 48B, keeps every row 16B-aligned */

#define BETA_F  6.99665877f      /* pi*sqrt(4.96) */
#define BETA2_F 48.9532378f      /* pi^2*4.96 */

typedef unsigned long long u64;

/* batch-innermost scratch: g_grid[(cell)*NB + b], g_T1[(yout*OSN + x)*NB + b] (complex) */
__device__ __align__(16) float g_grid[OSN * OSN * NB * 2];
__device__ __align__(16) float g_T1[RESN * OSN * NB * 2];
__device__ __align__(16) float2 g_E[OSN];
__device__ __align__(16) float  g_apod[RESN];

/* ---------------- packed f32x2 helpers ---------------- */
__device__ __forceinline__ u64 dup2(float x) {
    u64 r; asm("mov.b64 %0, {%1, %1};" : "=l"(r) : "f"(x)); return r;
}
__device__ __forceinline__ void unpack2(u64 p, float& lo, float& hi) {
    asm("mov.b64 {%0, %1}, %2;" : "=f"(lo), "=f"(hi) : "l"(p));
}
__device__ __forceinline__ u64 fma2(u64 a, u64 b, u64 c) {
    u64 d; asm("fma.rn.f32x2 %0, %1, %2, %3;" : "=l"(d) : "l"(a), "l"(b), "l"(c)); return d;
}

__device__ __forceinline__ void red_add_v4(float* p, float a, float b, float c, float d) {
    asm volatile("red.global.add.v4.f32 [%0], {%1, %2, %3, %4};"
                 :: "l"(p), "f"(a), "f"(b), "f"(c), "f"(d) : "memory");
}

/* ---------------- Bessel I0 (A&S 9.8.1 / 9.8.2) ---------------- */
__device__ __forceinline__ float i0f_dev(float x) {
    if (x < 3.75f) {
        float t = x * (1.0f / 3.75f);
        t *= t;
        return 1.0f + t * (3.5156229f + t * (3.0899424f + t * (1.2067492f
             + t * (0.2659732f + t * (0.0360768f + t * 0.0045813f)))));
    } else {
        float t = 3.75f / x;
        float p = 0.39894228f + t * (0.01328592f + t * (0.00225319f + t * (-0.00157565f
                + t * (0.00916281f + t * (-0.02057706f + t * (0.02635537f
                + t * (-0.01647633f + t * 0.00392377f)))))));
        return expf(x) * rsqrtf(x) * p;
    }
}

__device__ __forceinline__ float kbw(float delta) {
    float u  = delta * 0.5f;
    float tt = fmaxf(1.0f - u * u, 0.0f);
    return i0f_dev(BETA_F * sqrtf(tt)) * 0.25f;
}

__device__ __forceinline__ float2 cmul(float2 a, float2 b) {
    return make_float2(fmaf(a.x, b.x, -a.y * b.y), fmaf(a.x, b.y, a.y * b.x));
}

/* ------ kernel 1: zero the scatter grid + build twiddle/apod tables ------ */
__global__ void zero_grid_kernel() {
    int i = blockIdx.x * blockDim.x + threadIdx.x;
    if (i < OSN * OSN * NB * 2 / 4)
        ((float4*)g_grid)[i] = make_float4(0.f, 0.f, 0.f, 0.f);
    if (blockIdx.x == 0) {
        for (int k = threadIdx.x; k < OSN; k += blockDim.x) {
            float sv, cv;
            sincospif((float)k * (1.0f / 200.0f), &sv, &cv);
            g_E[k] = make_float2(cv, sv);
        }
        for (int k = threadIdx.x; k < RESN; k += blockDim.x) {
            float d = (float)(k - 160) * 0.0314159265f;
            float a = sqrtf(fmaxf(BETA2_F - d * d, 1e-12f));
            g_apod[k] = a / sinhf(a);
        }
    }
}

/* -- kernel 2: bilinear sample + KB scatter, thread = (point, batch-pair) --
   Grid layout is batch-innermost, so lanes 0-7 (same m, bp 0-7) write one
   contiguous 128B segment per cell -> coalesced red.add.v4. Weights are
   computed once per thread and reused for both batches. */
__global__ void grid_scatter_kernel(const float* __restrict__ ksp,
                                    const float* __restrict__ traj) {
    int idx = blockIdx.x * blockDim.x + threadIdx.x;
    if (idx >= MTRAJ * 8) return;
    int bp = idx & 7;          /* batch pair: handles b = 2bp, 2bp+1 */
    int m  = idx >> 3;

    float t0 = traj[2 * m + 0];
    float t1 = traj[2 * m + 1];

    /* bilinear sample of (2-ch) k-space image: t0 -> x, t1 -> y */
    float px = (t0 * (1.0f / 160.0f) + 1.0f) * 0.5f * 319.0f;
    float py = (t1 * (1.0f / 160.0f) + 1.0f) * 0.5f * 319.0f;
    float x0f = floorf(px), y0f = floorf(py);
    float wx1 = px - x0f,   wy1 = py - y0f;
    int   x0  = (int)x0f,   y0  = (int)y0f;

    const float* img0 = ksp + (size_t)(2 * bp) * (RESN * RESN * 2);
    const float* img1 = img0 + RESN * RESN * 2;
    float yr0 = 0.f, yi0 = 0.f, yr1 = 0.f, yi1 = 0.f;
#pragma unroll
    for (int dy = 0; dy < 2; dy++) {
#pragma unroll
        for (int dx = 0; dx < 2; dx++) {
            int  xi  = x0 + dx, yv = y0 + dy;
            float w  = (dx ? wx1 : 1.0f - wx1) * (dy ? wy1 : 1.0f - wy1);
            bool inb = (xi >= 0) && (xi < RESN) && (yv >= 0) && (yv < RESN);
            int  xc  = min(max(xi, 0), RESN - 1);
            int  yc  = min(max(yv, 0), RESN - 1);
            size_t off = ((size_t)yc * RESN + xc) * 2;
            float2 v0 = *(const float2*)(img0 + off);
            float2 v1 = *(const float2*)(img1 + off);
            float wm = inb ? w : 0.0f;
            yr0 += v0.x * wm;  yi0 += v0.y * wm;
            yr1 += v1.x * wm;  yi1 += v1.y * wm;
        }
    }

    /* KB gridding: coord column 0 -> grid ROW (y), column 1 -> grid COL (x) */
    float cy = t0 * 1.25f + 200.0f;
    float cx = t1 * 1.25f + 200.0f;
    int sy = (int)ceilf(cy - 2.0f);
    int sx = (int)ceilf(cx - 2.0f);

    float wy[4], wx[4];
    int   iy[4], ix[4];
#pragma unroll
    for (int j = 0; j < 4; j++) {
        wy[j] = kbw(cy - (float)(sy + j));
        wx[j] = kbw(cx - (float)(sx + j));
        int a = sy + j; if (a < 0) a += OSN; if (a >= OSN) a -= OSN; iy[j] = a;
        int c = sx + j; if (c < 0) c += OSN; if (c >= OSN) c -= OSN; ix[j] = c;
    }

    float* gb = g_grid + 4 * bp;   /* batch-pair offset inside cell */
#pragma unroll
    for (int jy = 0; jy < 4; jy++) {
#pragma unroll
        for (int jx = 0; jx < 4; jx++) {
            float w = wy[jy] * wx[jx];
            float* cell = gb + ((size_t)iy[jy] * OSN + ix[jx]) * (NB * 2);
            red_add_v4(cell, yr0 * w, yi0 * w, yr1 * w, yi1 * w);
        }
    }
}

/* --------------- centered 400-pt DFT, Cooley-Tukey 20x20 ---------------
   out[t] = sum_m x[m] * E[(m-200)(t-160) mod 400],  E[p] = exp(+2i*pi*p/400)
   Pass 1: DFT over y, one grid column x per block (8 batch lanes).
   Pass 2: DFT over x, one output row y_out per block (8 batch lanes);
           fully coalesced loads and final stores.
   Twiddle/apod tables precomputed (no transcendental prologue -> lower
   register pressure, targeting <=48 regs = 3 CTAs/SM). Inner MAC: R5
   configuration (packed fma.rn.f32x2 + LDS.128, twiddle dup2'd per step,
   scalar cmul recurrence).
------------------------------------------------------------------------ */

struct DftAcc { u64 X[4]; u64 Y[4]; };

#define DFT_MAC20(A, bx, by, stride_f, w0, step)                                 \
    {                                                                            \
        float2 w = (w0);                                                         \
        _Pragma("unroll")                                                        \
        for (int mm = 0; mm < 20; mm++) {                                        \
            u64 wxp  = dup2(w.x);                                                \
            u64 wyp  = dup2(w.y);                                                \
            u64 nwyp = dup2(-w.y);                                               \
            const float* px_ = (bx) + mm * (stride_f);                           \
            const float* py_ = (by) + mm * (stride_f);                           \
            ulonglong2 aX0 = *(const ulonglong2*)(px_);                          \
            ulonglong2 aY0 = *(const ulonglong2*)(py_);                          \
            ulonglong2 aX1 = *(const ulonglong2*)(px_ + 4);                      \
            ulonglong2 aY1 = *(const ulonglong2*)(py_ + 4);                      \
            A.X[0] = fma2(aY0.x, nwyp, fma2(aX0.x, wxp, A.X[0]));                \
            A.Y[0] = fma2(aY0.x, wxp,  fma2(aX0.x, wyp, A.Y[0]));                \
            A.X[1] = fma2(aY0.y, nwyp, fma2(aX0.y, wxp, A.X[1]));                \
            A.Y[1] = fma2(aY0.y, wxp,  fma2(aX0.y, wyp, A.Y[1]));                \
            A.X[2] = fma2(aY1.x, nwyp, fma2(aX1.x, wxp, A.X[2]));                \
            A.Y[2] = fma2(aY1.x, wxp,  fma2(aX1.x, wyp, A.Y[2]));                \
            A.X[3] = fma2(aY1.y, nwyp, fma2(aX1.y, wxp, A.X[3]));                \
            A.Y[3] = fma2(aY1.y, wxp,  fma2(aX1.y, wyp, A.Y[3]));                \
            w = cmul(w, step);                                                   \
        }                                                                        \
    }

/* pass 1: DFT over y for grid column x; 8 batch lanes per block */
__global__ void row_dft_kernel() {
    extern __shared__ float sh[];
    float*  xs_x = sh;
    float*  xs_y = sh + OSN * LSTR;
    float2* E    = (float2*)(sh + 2 * OSN * LSTR);

    int t  = threadIdx.x;                   /* 0..399 = y */
    int x  = blockIdx.x >> 1;
    int b0 = (blockIdx.x & 1) * 8;

    const float4* gp4 = (const float4*)(g_grid + (((size_t)t * OSN + x) * NB + b0) * 2);
#pragma unroll
    for (int k = 0; k < 4; k++) {
        float4 v = gp4[k];                  /* batches b0+2k, b0+2k+1 */
        xs_x[t * LSTR + 2 * k]     = v.x;
        xs_y[t * LSTR + 2 * k]     = v.y;
        xs_x[t * LSTR + 2 * k + 1] = v.z;
        xs_y[t * LSTR + 2 * k + 1] = v.w;
    }
    E[t] = g_E[t];
    __syncthreads();

    /* stage 1: thread (m2 = t/20, q = t%20) -> S row (m2*20+q)==t (in place) */
    int m2 = t / 20, q = t % 20;
    DftAcc A;
#pragma unroll
    for (int p = 0; p < 4; p++) { A.X[p] = 0; A.Y[p] = 0; }
    {
        float2 step = E[20 * q];
        DFT_MAC20(A, xs_x + m2 * LSTR, xs_y + m2 * LSTR, 20 * LSTR,
                  make_float2(1.f, 0.f), step);
    }
    __syncthreads();
    {
        int srow = t * LSTR;
#pragma unroll
        for (int p = 0; p < 4; p++) {
            *(u64*)(xs_x + srow + 2 * p) = A.X[p];
            *(u64*)(xs_y + srow + 2 * p) = A.Y[p];
        }
    }
    __syncthreads();

    /* stage 2: thread (q2 = t/16, j = t%16) -> y_out = 20*j + q2 */
    if (t < RESN) {
        int q2 = t / 16, j = t & 15;
        int tout = 20 * j + q2;
        int s = tout + 240; if (s >= OSN) s -= OSN;
        DftAcc B;
#pragma unroll
        for (int p = 0; p < 4; p++) { B.X[p] = 0; B.Y[p] = 0; }
        DFT_MAC20(B, xs_x + q2 * LSTR, xs_y + q2 * LSTR, 20 * LSTR,
                  make_float2((q2 & 1) ? -1.f : 1.f, 0.f), E[s]);

        float4* Tv = (float4*)(g_T1 + (((size_t)tout * OSN + x) * NB + b0) * 2);
#pragma unroll
        for (int p = 0; p < 4; p++) {
            float xr0, xr1, xi0, xi1;
            unpack2(B.X[p], xr0, xr1);
            unpack2(B.Y[p], xi0, xi1);
            Tv[p] = make_float4(xr0, xi0, xr1, xi1);
        }
    }
}

/* pass 2: DFT over x for output row y_out; coalesced loads + stores */
__global__ void col_dft_kernel(float* __restrict__ out) {
    extern __shared__ float sh[];
    float*  xs_x = sh;
    float*  xs_y = sh + OSN * LSTR;
    float2* E    = (float2*)(sh + 2 * OSN * LSTR);
    float*  apod = sh + 2 * OSN * LSTR + 2 * OSN;

    int t  = threadIdx.x;                   /* 0..399 = x */
    int yo = blockIdx.x >> 1;
    int b0 = (blockIdx.x & 1) * 8;

    const float4* Tp4 = (const float4*)(g_T1 + (((size_t)yo * OSN + t) * NB + b0) * 2);
#pragma unroll
    for (int k = 0; k < 4; k++) {
        float4 v = Tp4[k];
        xs_x[t * LSTR + 2 * k]     = v.x;
        xs_y[t * LSTR + 2 * k]     = v.y;
        xs_x[t * LSTR + 2 * k + 1] = v.z;
        xs_y[t * LSTR + 2 * k + 1] = v.w;
    }
    E[t] = g_E[t];
    if (t < RESN) apod[t] = g_apod[t];
    __syncthreads();

    /* stage 1 (in place) */
    int m2 = t / 20, q = t % 20;
    DftAcc A;
#pragma unroll
    for (int p = 0; p < 4; p++) { A.X[p] = 0; A.Y[p] = 0; }
    {
        float2 step = E[20 * q];
        DFT_MAC20(A, xs_x + m2 * LSTR, xs_y + m2 * LSTR, 20 * LSTR,
                  make_float2(1.f, 0.f), step);
    }
    __syncthreads();
    {
        int srow = t * LSTR;
#pragma unroll
        for (int p = 0; p < 4; p++) {
            *(u64*)(xs_x + srow + 2 * p) = A.X[p];
            *(u64*)(xs_y + srow + 2 * p) = A.Y[p];
        }
    }
    __syncthreads();

    /* stage 2 + apodization + coalesced final store */
    if (t < RESN) {
        int q2 = t / 16, j = t & 15;
        int tout = 20 * j + q2;              /* x_out */
        int s = tout + 240; if (s >= OSN) s -= OSN;
        DftAcc B;
#pragma unroll
        for (int p = 0; p < 4; p++) { B.X[p] = 0; B.Y[p] = 0; }
        DFT_MAC20(B, xs_x + q2 * LSTR, xs_y + q2 * LSTR, 20 * LSTR,
                  make_float2((q2 & 1) ? -1.f : 1.f, 0.f), E[s]);

        float f = apod[tout] * apod[yo] * (1.0f / 320.0f);

        float xr[GL], xi[GL];
#pragma unroll
        for (int p = 0; p < 4; p++) {
            unpack2(B.X[p], xr[2 * p], xr[2 * p + 1]);
            unpack2(B.Y[p], xi[2 * p], xi[2 * p + 1]);
        }

        /* out[b][0][c][yo][x_out]; consecutive threads -> consecutive x_out */
#pragma unroll
        for (int l = 0; l < GL; l++) {
            int b = b0 + l;
            float* po = out + (((size_t)b * 2) * RESN + yo) * RESN + tout;
            po[0]               = xr[l] * f;
            po[RESN * RESN]     = xi[l] * f;
        }
    }
}

extern "C" void kernel_launch(void* const* d_in, const int* in_sizes, int n_in,
                              void* d_out, int out_size) {
    const float* ksp  = (const float*)d_in[0];
    const float* traj = (const float*)d_in[1];
    float* out = (float*)d_out;

    const int SMEM_ROW = (2 * OSN * LSTR + 2 * OSN) * (int)sizeof(float);   /* 41600 B */
    const int SMEM_COL = SMEM_ROW + RESN * (int)sizeof(float);              /* 42880 B */

    cudaFuncSetAttribute(row_dft_kernel, cudaFuncAttributeMaxDynamicSharedMemorySize, SMEM_ROW);
    cudaFuncSetAttribute(col_dft_kernel, cudaFuncAttributeMaxDynamicSharedMemorySize, SMEM_COL);

    zero_grid_kernel<<<(OSN * OSN * NB * 2 / 4 + 255) / 256, 256>>>();
    grid_scatter_kernel<<<(MTRAJ * 8 + 255) / 256, 256>>>(ksp, traj);
    row_dft_kernel<<<OSN * 2, OSN, SMEM_ROW>>>();
    col_dft_kernel<<<RESN * 2, OSN, SMEM_COL>>>(out);
}

// round 15
// speedup vs baseline: 1.5909x; 1.5909x over previous
#include <cuda_runtime.h>
#include <math.h>

#define RESN   320
#define MTRAJ  25600
#define NB     16
#define OSN    400
#define GL     8
#define LSTR   12   /* lane-stride in floats: 48B, keeps every row 16B-aligned */

#define BETA_F  6.99665877f      /* pi*sqrt(4.96) */
#define BETA2_F 48.9532378f      /* pi^2*4.96 */

typedef unsigned long long u64;

/* batch-innermost scratch: g_grid[(cell)*NB + b], g_T1[(yout*OSN + x)*NB + b] (complex) */
__device__ __align__(16) float g_grid[OSN * OSN * NB * 2];
__device__ __align__(16) float g_T1[RESN * OSN * NB * 2];
__device__ __align__(16) float2 g_E[OSN];
__device__ __align__(16) float  g_apod[RESN];

/* ---------------- packed f32x2 helpers ---------------- */
__device__ __forceinline__ u64 dup2(float x) {
    u64 r; asm("mov.b64 %0, {%1, %1};" : "=l"(r) : "f"(x)); return r;
}
__device__ __forceinline__ void unpack2(u64 p, float& lo, float& hi) {
    asm("mov.b64 {%0, %1}, %2;" : "=f"(lo), "=f"(hi) : "l"(p));
}
__device__ __forceinline__ u64 fma2(u64 a, u64 b, u64 c) {
    u64 d; asm("fma.rn.f32x2 %0, %1, %2, %3;" : "=l"(d) : "l"(a), "l"(b), "l"(c)); return d;
}

__device__ __forceinline__ void red_add_v4(float* p, float a, float b, float c, float d) {
    asm volatile("red.global.add.v4.f32 [%0], {%1, %2, %3, %4};"
                 :: "l"(p), "f"(a), "f"(b), "f"(c), "f"(d) : "memory");
}

/* ---------------- Bessel I0 (A&S 9.8.1 / 9.8.2) ---------------- */
__device__ __forceinline__ float i0f_dev(float x) {
    if (x < 3.75f) {
        float t = x * (1.0f / 3.75f);
        t *= t;
        return 1.0f + t * (3.5156229f + t * (3.0899424f + t * (1.2067492f
             + t * (0.2659732f + t * (0.0360768f + t * 0.0045813f)))));
    } else {
        float t = 3.75f / x;
        float p = 0.39894228f + t * (0.01328592f + t * (0.00225319f + t * (-0.00157565f
                + t * (0.00916281f + t * (-0.02057706f + t * (0.02635537f
                + t * (-0.01647633f + t * 0.00392377f)))))));
        return expf(x) * rsqrtf(x) * p;
    }
}

__device__ __forceinline__ float kbw(float delta) {
    float u  = delta * 0.5f;
    float tt = fmaxf(1.0f - u * u, 0.0f);
    return i0f_dev(BETA_F * sqrtf(tt)) * 0.25f;
}

__device__ __forceinline__ float2 cmul(float2 a, float2 b) {
    return make_float2(fmaf(a.x, b.x, -a.y * b.y), fmaf(a.x, b.y, a.y * b.x));
}

/* ------ kernel 1: zero the scatter grid + build twiddle/apod tables ------ */
__global__ void zero_grid_kernel() {
    int i = blockIdx.x * blockDim.x + threadIdx.x;
    if (i < OSN * OSN * NB * 2 / 4)
        ((float4*)g_grid)[i] = make_float4(0.f, 0.f, 0.f, 0.f);
    if (blockIdx.x == 0) {
        for (int k = threadIdx.x; k < OSN; k += blockDim.x) {
            float sv, cv;
            sincospif((float)k * (1.0f / 200.0f), &sv, &cv);
            g_E[k] = make_float2(cv, sv);
        }
        for (int k = threadIdx.x; k < RESN; k += blockDim.x) {
            float d = (float)(k - 160) * 0.0314159265f;
            float a = sqrtf(fmaxf(BETA2_F - d * d, 1e-12f));
            g_apod[k] = a / sinhf(a);
        }
    }
}

/* -- kernel 2: bilinear sample + KB scatter, thread = (point, batch-pair) --
   Grid layout is batch-innermost, so lanes 0-7 (same m, bp 0-7) write one
   contiguous 128B segment per cell -> coalesced red.add.v4. Weights are
   computed once per thread and reused for both batches. */
__global__ void grid_scatter_kernel(const float* __restrict__ ksp,
                                    const float* __restrict__ traj) {
    int idx = blockIdx.x * blockDim.x + threadIdx.x;
    if (idx >= MTRAJ * 8) return;
    int bp = idx & 7;          /* batch pair: handles b = 2bp, 2bp+1 */
    int m  = idx >> 3;

    float t0 = traj[2 * m + 0];
    float t1 = traj[2 * m + 1];

    /* bilinear sample of (2-ch) k-space image: t0 -> x, t1 -> y */
    float px = (t0 * (1.0f / 160.0f) + 1.0f) * 0.5f * 319.0f;
    float py = (t1 * (1.0f / 160.0f) + 1.0f) * 0.5f * 319.0f;
    float x0f = floorf(px), y0f = floorf(py);
    float wx1 = px - x0f,   wy1 = py - y0f;
    int   x0  = (int)x0f,   y0  = (int)y0f;

    const float* img0 = ksp + (size_t)(2 * bp) * (RESN * RESN * 2);
    const float* img1 = img0 + RESN * RESN * 2;
    float yr0 = 0.f, yi0 = 0.f, yr1 = 0.f, yi1 = 0.f;
#pragma unroll
    for (int dy = 0; dy < 2; dy++) {
#pragma unroll
        for (int dx = 0; dx < 2; dx++) {
            int  xi  = x0 + dx, yv = y0 + dy;
            float w  = (dx ? wx1 : 1.0f - wx1) * (dy ? wy1 : 1.0f - wy1);
            bool inb = (xi >= 0) && (xi < RESN) && (yv >= 0) && (yv < RESN);
            int  xc  = min(max(xi, 0), RESN - 1);
            int  yc  = min(max(yv, 0), RESN - 1);
            size_t off = ((size_t)yc * RESN + xc) * 2;
            float2 v0 = *(const float2*)(img0 + off);
            float2 v1 = *(const float2*)(img1 + off);
            float wm = inb ? w : 0.0f;
            yr0 += v0.x * wm;  yi0 += v0.y * wm;
            yr1 += v1.x * wm;  yi1 += v1.y * wm;
        }
    }

    /* KB gridding: coord column 0 -> grid ROW (y), column 1 -> grid COL (x) */
    float cy = t0 * 1.25f + 200.0f;
    float cx = t1 * 1.25f + 200.0f;
    int sy = (int)ceilf(cy - 2.0f);
    int sx = (int)ceilf(cx - 2.0f);

    float wy[4], wx[4];
    int   iy[4], ix[4];
#pragma unroll
    for (int j = 0; j < 4; j++) {
        wy[j] = kbw(cy - (float)(sy + j));
        wx[j] = kbw(cx - (float)(sx + j));
        int a = sy + j; if (a < 0) a += OSN; if (a >= OSN) a -= OSN; iy[j] = a;
        int c = sx + j; if (c < 0) c += OSN; if (c >= OSN) c -= OSN; ix[j] = c;
    }

    float* gb = g_grid + 4 * bp;   /* batch-pair offset inside cell */
#pragma unroll
    for (int jy = 0; jy < 4; jy++) {
#pragma unroll
        for (int jx = 0; jx < 4; jx++) {
            float w = wy[jy] * wx[jx];
            float* cell = gb + ((size_t)iy[jy] * OSN + ix[jx]) * (NB * 2);
            red_add_v4(cell, yr0 * w, yi0 * w, yr1 * w, yi1 * w);
        }
    }
}

/* --------------- centered 400-pt DFT, Cooley-Tukey 20x20 ---------------
   out[t] = sum_m x[m] * E[(m-200)(t-160) mod 400],  E[p] = exp(+2i*pi*p/400)
   Pass 1: DFT over y, one grid column x per block (8 batch lanes).
   Pass 2: DFT over x, one output row y_out per block (8 batch lanes);
           fully coalesced loads and final stores.
   Twiddle/apod tables precomputed. Inner MAC: R5 configuration (packed
   fma.rn.f32x2 + LDS.128, twiddle dup2'd per step, scalar cmul recurrence).
------------------------------------------------------------------------ */

struct DftAcc { u64 X[4]; u64 Y[4]; };

#define DFT_MAC20(A, bx, by, stride_f, w0, step)                                 \
    {                                                                            \
        float2 w = (w0);                                                         \
        _Pragma("unroll")                                                        \
        for (int mm = 0; mm < 20; mm++) {                                        \
            u64 wxp  = dup2(w.x);                                                \
            u64 wyp  = dup2(w.y);                                                \
            u64 nwyp = dup2(-w.y);                                               \
            const float* px_ = (bx) + mm * (stride_f);                           \
            const float* py_ = (by) + mm * (stride_f);                           \
            ulonglong2 aX0 = *(const ulonglong2*)(px_);                          \
            ulonglong2 aY0 = *(const ulonglong2*)(py_);                          \
            ulonglong2 aX1 = *(const ulonglong2*)(px_ + 4);                      \
            ulonglong2 aY1 = *(const ulonglong2*)(py_ + 4);                      \
            A.X[0] = fma2(aY0.x, nwyp, fma2(aX0.x, wxp, A.X[0]));                \
            A.Y[0] = fma2(aY0.x, wxp,  fma2(aX0.x, wyp, A.Y[0]));                \
            A.X[1] = fma2(aY0.y, nwyp, fma2(aX0.y, wxp, A.X[1]));                \
            A.Y[1] = fma2(aY0.y, wxp,  fma2(aX0.y, wyp, A.Y[1]));                \
            A.X[2] = fma2(aY1.x, nwyp, fma2(aX1.x, wxp, A.X[2]));                \
            A.Y[2] = fma2(aY1.x, wxp,  fma2(aX1.x, wyp, A.Y[2]));                \
            A.X[3] = fma2(aY1.y, nwyp, fma2(aX1.y, wxp, A.X[3]));                \
            A.Y[3] = fma2(aY1.y, wxp,  fma2(aX1.y, wyp, A.Y[3]));                \
            w = cmul(w, step);                                                   \
        }                                                                        \
    }

/* pass 1: DFT over y for grid column x; 8 batch lanes per block */
__global__ void row_dft_kernel() {
    extern __shared__ float sh[];
    float*  xs_x = sh;
    float*  xs_y = sh + OSN * LSTR;
    float2* E    = (float2*)(sh + 2 * OSN * LSTR);

    int t  = threadIdx.x;                   /* 0..399 = y */
    int x  = blockIdx.x >> 1;
    int b0 = (blockIdx.x & 1) * 8;

    const float4* gp4 = (const float4*)(g_grid + (((size_t)t * OSN + x) * NB + b0) * 2);
#pragma unroll
    for (int k = 0; k < 4; k++) {
        float4 v = gp4[k];                  /* batches b0+2k, b0+2k+1 */
        xs_x[t * LSTR + 2 * k]     = v.x;
        xs_y[t * LSTR + 2 * k]     = v.y;
        xs_x[t * LSTR + 2 * k + 1] = v.z;
        xs_y[t * LSTR + 2 * k + 1] = v.w;
    }
    E[t] = g_E[t];
    __syncthreads();

    /* stage 1: thread (m2 = t/20, q = t%20) -> S row (m2*20+q)==t (in place) */
    int m2 = t / 20, q = t % 20;
    DftAcc A;
#pragma unroll
    for (int p = 0; p < 4; p++) { A.X[p] = 0; A.Y[p] = 0; }
    {
        float2 step = E[20 * q];
        DFT_MAC20(A, xs_x + m2 * LSTR, xs_y + m2 * LSTR, 20 * LSTR,
                  make_float2(1.f, 0.f), step);
    }
    __syncthreads();
    {
        int srow = t * LSTR;
#pragma unroll
        for (int p = 0; p < 4; p++) {
            *(u64*)(xs_x + srow + 2 * p) = A.X[p];
            *(u64*)(xs_y + srow + 2 * p) = A.Y[p];
        }
    }
    __syncthreads();

    /* stage 2: thread (q2 = t/16, j = t%16) -> y_out = 20*j + q2 */
    if (t < RESN) {
        int q2 = t / 16, j = t & 15;
        int tout = 20 * j + q2;
        int s = tout + 240; if (s >= OSN) s -= OSN;
        DftAcc B;
#pragma unroll
        for (int p = 0; p < 4; p++) { B.X[p] = 0; B.Y[p] = 0; }
        DFT_MAC20(B, xs_x + q2 * LSTR, xs_y + q2 * LSTR, 20 * LSTR,
                  make_float2((q2 & 1) ? -1.f : 1.f, 0.f), E[s]);

        float4* Tv = (float4*)(g_T1 + (((size_t)tout * OSN + x) * NB + b0) * 2);
#pragma unroll
        for (int p = 0; p < 4; p++) {
            float xr0, xr1, xi0, xi1;
            unpack2(B.X[p], xr0, xr1);
            unpack2(B.Y[p], xi0, xi1);
            Tv[p] = make_float4(xr0, xi0, xr1, xi1);
        }
    }
}

/* pass 2: DFT over x for output row y_out; coalesced loads + stores */
__global__ void col_dft_kernel(float* __restrict__ out) {
    extern __shared__ float sh[];
    float*  xs_x = sh;
    float*  xs_y = sh + OSN * LSTR;
    float2* E    = (float2*)(sh + 2 * OSN * LSTR);
    float*  apod = sh + 2 * OSN * LSTR + 2 * OSN;

    int t  = threadIdx.x;                   /* 0..399 = x */
    int yo = blockIdx.x >> 1;
    int b0 = (blockIdx.x & 1) * 8;

    const float4* Tp4 = (const float4*)(g_T1 + (((size_t)yo * OSN + t) * NB + b0) * 2);
#pragma unroll
    for (int k = 0; k < 4; k++) {
        float4 v = Tp4[k];
        xs_x[t * LSTR + 2 * k]     = v.x;
        xs_y[t * LSTR + 2 * k]     = v.y;
        xs_x[t * LSTR + 2 * k + 1] = v.z;
        xs_y[t * LSTR + 2 * k + 1] = v.w;
    }
    E[t] = g_E[t];
    if (t < RESN) apod[t] = g_apod[t];
    __syncthreads();

    /* stage 1 (in place) */
    int m2 = t / 20, q = t % 20;
    DftAcc A;
#pragma unroll
    for (int p = 0; p < 4; p++) { A.X[p] = 0; A.Y[p] = 0; }
    {
        float2 step = E[20 * q];
        DFT_MAC20(A, xs_x + m2 * LSTR, xs_y + m2 * LSTR, 20 * LSTR,
                  make_float2(1.f, 0.f), step);
    }
    __syncthreads();
    {
        int srow = t * LSTR;
#pragma unroll
        for (int p = 0; p < 4; p++) {
            *(u64*)(xs_x + srow + 2 * p) = A.X[p];
            *(u64*)(xs_y + srow + 2 * p) = A.Y[p];
        }
    }
    __syncthreads();

    /* stage 2 + apodization + coalesced final store */
    if (t < RESN) {
        int q2 = t / 16, j = t & 15;
        int tout = 20 * j + q2;              /* x_out */
        int s = tout + 240; if (s >= OSN) s -= OSN;
        DftAcc B;
#pragma unroll
        for (int p = 0; p < 4; p++) { B.X[p] = 0; B.Y[p] = 0; }
        DFT_MAC20(B, xs_x + q2 * LSTR, xs_y + q2 * LSTR, 20 * LSTR,
                  make_float2((q2 & 1) ? -1.f : 1.f, 0.f), E[s]);

        float f = apod[tout] * apod[yo] * (1.0f / 320.0f);

        float xr[GL], xi[GL];
#pragma unroll
        for (int p = 0; p < 4; p++) {
            unpack2(B.X[p], xr[2 * p], xr[2 * p + 1]);
            unpack2(B.Y[p], xi[2 * p], xi[2 * p + 1]);
        }

        /* out[b][0][c][yo][x_out]; consecutive threads -> consecutive x_out */
#pragma unroll
        for (int l = 0; l < GL; l++) {
            int b = b0 + l;
            float* po = out + (((size_t)b * 2) * RESN + yo) * RESN + tout;
            po[0]               = xr[l] * f;
            po[RESN * RESN]     = xi[l] * f;
        }
    }
}

extern "C" void kernel_launch(void* const* d_in, const int* in_sizes, int n_in,
                              void* d_out, int out_size) {
    const float* ksp  = (const float*)d_in[0];
    const float* traj = (const float*)d_in[1];
    float* out = (float*)d_out;

    const int SMEM_ROW = (2 * OSN * LSTR + 2 * OSN) * (int)sizeof(float);   /* 41600 B */
    const int SMEM_COL = SMEM_ROW + RESN * (int)sizeof(float);              /* 42880 B */

    cudaFuncSetAttribute(row_dft_kernel, cudaFuncAttributeMaxDynamicSharedMemorySize, SMEM_ROW);
    cudaFuncSetAttribute(col_dft_kernel, cudaFuncAttributeMaxDynamicSharedMemorySize, SMEM_COL);

    zero_grid_kernel<<<(OSN * OSN * NB * 2 / 4 + 255) / 256, 256>>>();
    grid_scatter_kernel<<<(MTRAJ * 8 + 255) / 256, 256>>>(ksp, traj);
    row_dft_kernel<<<OSN * 2, OSN, SMEM_ROW>>>();
    col_dft_kernel<<<RESN * 2, OSN, SMEM_COL>>>(out);
}

// round 16
// speedup vs baseline: 1.6373x; 1.0292x over previous
#include <cuda_runtime.h>
#include <math.h>

#define RESN   320
#define MTRAJ  25600
#define NB     16
#define OSN    400
#define GL     8
#define LSTR   12   /* lane-stride in floats: 48B, keeps every row 16B-aligned */

#define BETA_F  6.99665877f      /* pi*sqrt(4.96) */
#define BETA2_F 48.9532378f      /* pi^2*4.96 */

typedef unsigned long long u64;

/* batch-innermost scratch: g_grid[(cell)*NB + b], g_T1[(yout*OSN + x)*NB + b] (complex) */
__device__ __align__(16) float g_grid[OSN * OSN * NB * 2];
__device__ __align__(16) float g_T1[RESN * OSN * NB * 2];
__device__ __align__(16) float2 g_E[OSN];
__device__ __align__(16) float  g_apod[RESN];

/* ---------------- packed f32x2 helpers ---------------- */
__device__ __forceinline__ u64 dup2(float x) {
    u64 r; asm("mov.b64 %0, {%1, %1};" : "=l"(r) : "f"(x)); return r;
}
__device__ __forceinline__ void unpack2(u64 p, float& lo, float& hi) {
    asm("mov.b64 {%0, %1}, %2;" : "=f"(lo), "=f"(hi) : "l"(p));
}
__device__ __forceinline__ u64 fma2(u64 a, u64 b, u64 c) {
    u64 d; asm("fma.rn.f32x2 %0, %1, %2, %3;" : "=l"(d) : "l"(a), "l"(b), "l"(c)); return d;
}

__device__ __forceinline__ void red_add_v4(float* p, float a, float b, float c, float d) {
    asm volatile("red.global.add.v4.f32 [%0], {%1, %2, %3, %4};"
                 :: "l"(p), "f"(a), "f"(b), "f"(c), "f"(d) : "memory");
}

/* ---------------- Bessel I0 (A&S 9.8.1 / 9.8.2) ---------------- */
__device__ __forceinline__ float i0f_dev(float x) {
    if (x < 3.75f) {
        float t = x * (1.0f / 3.75f);
        t *= t;
        return 1.0f + t * (3.5156229f + t * (3.0899424f + t * (1.2067492f
             + t * (0.2659732f + t * (0.0360768f + t * 0.0045813f)))));
    } else {
        float t = 3.75f / x;
        float p = 0.39894228f + t * (0.01328592f + t * (0.00225319f + t * (-0.00157565f
                + t * (0.00916281f + t * (-0.02057706f + t * (0.02635537f
                + t * (-0.01647633f + t * 0.00392377f)))))));
        return expf(x) * rsqrtf(x) * p;
    }
}

__device__ __forceinline__ float kbw(float delta) {
    float u  = delta * 0.5f;
    float tt = fmaxf(1.0f - u * u, 0.0f);
    return i0f_dev(BETA_F * sqrtf(tt)) * 0.25f;
}

__device__ __forceinline__ float2 cmul(float2 a, float2 b) {
    return make_float2(fmaf(a.x, b.x, -a.y * b.y), fmaf(a.x, b.y, a.y * b.x));
}

/* ------ kernel 1: zero the scatter grid + build twiddle/apod tables ------ */
__global__ void zero_grid_kernel() {
    int i = blockIdx.x * blockDim.x + threadIdx.x;
    if (i < OSN * OSN * NB * 2 / 4)
        ((float4*)g_grid)[i] = make_float4(0.f, 0.f, 0.f, 0.f);
    if (blockIdx.x == 0) {
        for (int k = threadIdx.x; k < OSN; k += blockDim.x) {
            float sv, cv;
            sincospif((float)k * (1.0f / 200.0f), &sv, &cv);
            g_E[k] = make_float2(cv, sv);
        }
        for (int k = threadIdx.x; k < RESN; k += blockDim.x) {
            float d = (float)(k - 160) * 0.0314159265f;
            float a = sqrtf(fmaxf(BETA2_F - d * d, 1e-12f));
            g_apod[k] = a / sinhf(a);
        }
    }
}

/* -- kernel 2: bilinear sample + KB scatter, thread = (point, batch-pair) --
   Grid layout is batch-innermost, so lanes 0-7 (same m, bp 0-7) write one
   contiguous 128B segment per cell -> coalesced red.add.v4. Weights are
   computed once per thread and reused for both batches. */
__global__ void grid_scatter_kernel(const float* __restrict__ ksp,
                                    const float* __restrict__ traj) {
    int idx = blockIdx.x * blockDim.x + threadIdx.x;
    if (idx >= MTRAJ * 8) return;
    int bp = idx & 7;          /* batch pair: handles b = 2bp, 2bp+1 */
    int m  = idx >> 3;

    float t0 = traj[2 * m + 0];
    float t1 = traj[2 * m + 1];

    /* bilinear sample of (2-ch) k-space image: t0 -> x, t1 -> y */
    float px = (t0 * (1.0f / 160.0f) + 1.0f) * 0.5f * 319.0f;
    float py = (t1 * (1.0f / 160.0f) + 1.0f) * 0.5f * 319.0f;
    float x0f = floorf(px), y0f = floorf(py);
    float wx1 = px - x0f,   wy1 = py - y0f;
    int   x0  = (int)x0f,   y0  = (int)y0f;

    const float* img0 = ksp + (size_t)(2 * bp) * (RESN * RESN * 2);
    const float* img1 = img0 + RESN * RESN * 2;
    float yr0 = 0.f, yi0 = 0.f, yr1 = 0.f, yi1 = 0.f;
#pragma unroll
    for (int dy = 0; dy < 2; dy++) {
#pragma unroll
        for (int dx = 0; dx < 2; dx++) {
            int  xi  = x0 + dx, yv = y0 + dy;
            float w  = (dx ? wx1 : 1.0f - wx1) * (dy ? wy1 : 1.0f - wy1);
            bool inb = (xi >= 0) && (xi < RESN) && (yv >= 0) && (yv < RESN);
            int  xc  = min(max(xi, 0), RESN - 1);
            int  yc  = min(max(yv, 0), RESN - 1);
            size_t off = ((size_t)yc * RESN + xc) * 2;
            float2 v0 = *(const float2*)(img0 + off);
            float2 v1 = *(const float2*)(img1 + off);
            float wm = inb ? w : 0.0f;
            yr0 += v0.x * wm;  yi0 += v0.y * wm;
            yr1 += v1.x * wm;  yi1 += v1.y * wm;
        }
    }

    /* KB gridding: coord column 0 -> grid ROW (y), column 1 -> grid COL (x) */
    float cy = t0 * 1.25f + 200.0f;
    float cx = t1 * 1.25f + 200.0f;
    int sy = (int)ceilf(cy - 2.0f);
    int sx = (int)ceilf(cx - 2.0f);

    float wy[4], wx[4];
    int   iy[4], ix[4];
#pragma unroll
    for (int j = 0; j < 4; j++) {
        wy[j] = kbw(cy - (float)(sy + j));
        wx[j] = kbw(cx - (float)(sx + j));
        int a = sy + j; if (a < 0) a += OSN; if (a >= OSN) a -= OSN; iy[j] = a;
        int c = sx + j; if (c < 0) c += OSN; if (c >= OSN) c -= OSN; ix[j] = c;
    }

    float* gb = g_grid + 4 * bp;   /* batch-pair offset inside cell */
#pragma unroll
    for (int jy = 0; jy < 4; jy++) {
#pragma unroll
        for (int jx = 0; jx < 4; jx++) {
            float w = wy[jy] * wx[jx];
            float* cell = gb + ((size_t)iy[jy] * OSN + ix[jx]) * (NB * 2);
            red_add_v4(cell, yr0 * w, yi0 * w, yr1 * w, yi1 * w);
        }
    }
}

/* --------------- centered 400-pt DFT, Cooley-Tukey 20x20 ---------------
   out[t] = sum_m x[m] * E[(m-200)(t-160) mod 400],  E[p] = exp(+2i*pi*p/400)
   Pass 1: DFT over y, one grid column x per block (8 batch lanes).
   Pass 2: DFT over x, one output row y_out per block (8 batch lanes);
           fully coalesced loads and final stores.
   __maxnreg__(48) pins the kernels at the 3-CTA/SM boundary (3*416*48 =
   59904 <= 64K) WITHOUT the launch_bounds snap-to-32 failure mode.
   Inner MAC: packed fma.rn.f32x2 + LDS.128, twiddle dup2'd per step,
   scalar cmul recurrence.
------------------------------------------------------------------------ */

struct DftAcc { u64 X[4]; u64 Y[4]; };

#define DFT_MAC20(A, bx, by, stride_f, w0, step)                                 \
    {                                                                            \
        float2 w = (w0);                                                         \
        _Pragma("unroll")                                                        \
        for (int mm = 0; mm < 20; mm++) {                                        \
            u64 wxp  = dup2(w.x);                                                \
            u64 wyp  = dup2(w.y);                                                \
            u64 nwyp = dup2(-w.y);                                               \
            const float* px_ = (bx) + mm * (stride_f);                           \
            const float* py_ = (by) + mm * (stride_f);                           \
            ulonglong2 aX0 = *(const ulonglong2*)(px_);                          \
            ulonglong2 aY0 = *(const ulonglong2*)(py_);                          \
            ulonglong2 aX1 = *(const ulonglong2*)(px_ + 4);                      \
            ulonglong2 aY1 = *(const ulonglong2*)(py_ + 4);                      \
            A.X[0] = fma2(aY0.x, nwyp, fma2(aX0.x, wxp, A.X[0]));                \
            A.Y[0] = fma2(aY0.x, wxp,  fma2(aX0.x, wyp, A.Y[0]));                \
            A.X[1] = fma2(aY0.y, nwyp, fma2(aX0.y, wxp, A.X[1]));                \
            A.Y[1] = fma2(aY0.y, wxp,  fma2(aX0.y, wyp, A.Y[1]));                \
            A.X[2] = fma2(aY1.x, nwyp, fma2(aX1.x, wxp, A.X[2]));                \
            A.Y[2] = fma2(aY1.x, wxp,  fma2(aX1.x, wyp, A.Y[2]));                \
            A.X[3] = fma2(aY1.y, nwyp, fma2(aX1.y, wxp, A.X[3]));                \
            A.Y[3] = fma2(aY1.y, wxp,  fma2(aX1.y, wyp, A.Y[3]));                \
            w = cmul(w, step);                                                   \
        }                                                                        \
    }

/* pass 1: DFT over y for grid column x; 8 batch lanes per block */
__global__ void __maxnreg__(48) row_dft_kernel() {
    extern __shared__ float sh[];
    float*  xs_x = sh;
    float*  xs_y = sh + OSN * LSTR;
    float2* E    = (float2*)(sh + 2 * OSN * LSTR);

    int t  = threadIdx.x;                   /* 0..399 = y */
    int x  = blockIdx.x >> 1;
    int b0 = (blockIdx.x & 1) * 8;

    const float4* gp4 = (const float4*)(g_grid + (((size_t)t * OSN + x) * NB + b0) * 2);
#pragma unroll
    for (int k = 0; k < 4; k++) {
        float4 v = gp4[k];                  /* batches b0+2k, b0+2k+1 */
        xs_x[t * LSTR + 2 * k]     = v.x;
        xs_y[t * LSTR + 2 * k]     = v.y;
        xs_x[t * LSTR + 2 * k + 1] = v.z;
        xs_y[t * LSTR + 2 * k + 1] = v.w;
    }
    E[t] = g_E[t];
    __syncthreads();

    /* stage 1: thread (m2 = t/20, q = t%20) -> S row (m2*20+q)==t (in place) */
    int m2 = t / 20, q = t % 20;
    DftAcc A;
#pragma unroll
    for (int p = 0; p < 4; p++) { A.X[p] = 0; A.Y[p] = 0; }
    {
        float2 step = E[20 * q];
        DFT_MAC20(A, xs_x + m2 * LSTR, xs_y + m2 * LSTR, 20 * LSTR,
                  make_float2(1.f, 0.f), step);
    }
    __syncthreads();
    {
        int srow = t * LSTR;
#pragma unroll
        for (int p = 0; p < 4; p++) {
            *(u64*)(xs_x + srow + 2 * p) = A.X[p];
            *(u64*)(xs_y + srow + 2 * p) = A.Y[p];
        }
    }
    __syncthreads();

    /* stage 2: thread (q2 = t/16, j = t%16) -> y_out = 20*j + q2 */
    if (t < RESN) {
        int q2 = t / 16, j = t & 15;
        int tout = 20 * j + q2;
        int s = tout + 240; if (s >= OSN) s -= OSN;
        DftAcc B;
#pragma unroll
        for (int p = 0; p < 4; p++) { B.X[p] = 0; B.Y[p] = 0; }
        DFT_MAC20(B, xs_x + q2 * LSTR, xs_y + q2 * LSTR, 20 * LSTR,
                  make_float2((q2 & 1) ? -1.f : 1.f, 0.f), E[s]);

        float4* Tv = (float4*)(g_T1 + (((size_t)tout * OSN + x) * NB + b0) * 2);
#pragma unroll
        for (int p = 0; p < 4; p++) {
            float xr0, xr1, xi0, xi1;
            unpack2(B.X[p], xr0, xr1);
            unpack2(B.Y[p], xi0, xi1);
            Tv[p] = make_float4(xr0, xi0, xr1, xi1);
        }
    }
}

/* pass 2: DFT over x for output row y_out; coalesced loads + stores */
__global__ void __maxnreg__(48) col_dft_kernel(float* __restrict__ out) {
    extern __shared__ float sh[];
    float*  xs_x = sh;
    float*  xs_y = sh + OSN * LSTR;
    float2* E    = (float2*)(sh + 2 * OSN * LSTR);
    float*  apod = sh + 2 * OSN * LSTR + 2 * OSN;

    int t  = threadIdx.x;                   /* 0..399 = x */
    int yo = blockIdx.x >> 1;
    int b0 = (blockIdx.x & 1) * 8;

    const float4* Tp4 = (const float4*)(g_T1 + (((size_t)yo * OSN + t) * NB + b0) * 2);
#pragma unroll
    for (int k = 0; k < 4; k++) {
        float4 v = Tp4[k];
        xs_x[t * LSTR + 2 * k]     = v.x;
        xs_y[t * LSTR + 2 * k]     = v.y;
        xs_x[t * LSTR + 2 * k + 1] = v.z;
        xs_y[t * LSTR + 2 * k + 1] = v.w;
    }
    E[t] = g_E[t];
    if (t < RESN) apod[t] = g_apod[t];
    __syncthreads();

    /* stage 1 (in place) */
    int m2 = t / 20, q = t % 20;
    DftAcc A;
#pragma unroll
    for (int p = 0; p < 4; p++) { A.X[p] = 0; A.Y[p] = 0; }
    {
        float2 step = E[20 * q];
        DFT_MAC20(A, xs_x + m2 * LSTR, xs_y + m2 * LSTR, 20 * LSTR,
                  make_float2(1.f, 0.f), step);
    }
    __syncthreads();
    {
        int srow = t * LSTR;
#pragma unroll
        for (int p = 0; p < 4; p++) {
            *(u64*)(xs_x + srow + 2 * p) = A.X[p];
            *(u64*)(xs_y + srow + 2 * p) = A.Y[p];
        }
    }
    __syncthreads();

    /* stage 2 + apodization + coalesced final store */
    if (t < RESN) {
        int q2 = t / 16, j = t & 15;
        int tout = 20 * j + q2;              /* x_out */
        int s = tout + 240; if (s >= OSN) s -= OSN;
        DftAcc B;
#pragma unroll
        for (int p = 0; p < 4; p++) { B.X[p] = 0; B.Y[p] = 0; }
        DFT_MAC20(B, xs_x + q2 * LSTR, xs_y + q2 * LSTR, 20 * LSTR,
                  make_float2((q2 & 1) ? -1.f : 1.f, 0.f), E[s]);

        float f = apod[tout] * apod[yo] * (1.0f / 320.0f);

        float xr[GL], xi[GL];
#pragma unroll
        for (int p = 0; p < 4; p++) {
            unpack2(B.X[p], xr[2 * p], xr[2 * p + 1]);
            unpack2(B.Y[p], xi[2 * p], xi[2 * p + 1]);
        }

        /* out[b][0][c][yo][x_out]; consecutive threads -> consecutive x_out */
#pragma unroll
        for (int l = 0; l < GL; l++) {
            int b = b0 + l;
            float* po = out + (((size_t)b * 2) * RESN + yo) * RESN + tout;
            po[0]               = xr[l] * f;
            po[RESN * RESN]     = xi[l] * f;
        }
    }
}

extern "C" void kernel_launch(void* const* d_in, const int* in_sizes, int n_in,
                              void* d_out, int out_size) {
    const float* ksp  = (const float*)d_in[0];
    const float* traj = (const float*)d_in[1];
    float* out = (float*)d_out;

    const int SMEM_ROW = (2 * OSN * LSTR + 2 * OSN) * (int)sizeof(float);   /* 41600 B */
    const int SMEM_COL = SMEM_ROW + RESN * (int)sizeof(float);              /* 42880 B */

    cudaFuncSetAttribute(row_dft_kernel, cudaFuncAttributeMaxDynamicSharedMemorySize, SMEM_ROW);
    cudaFuncSetAttribute(col_dft_kernel, cudaFuncAttributeMaxDynamicSharedMemorySize, SMEM_COL);

    zero_grid_kernel<<<(OSN * OSN * NB * 2 / 4 + 255) / 256, 256>>>();
    grid_scatter_kernel<<<(MTRAJ * 8 + 255) / 256, 256>>>(ksp, traj);
    row_dft_kernel<<<OSN * 2, OSN, SMEM_ROW>>>();
    col_dft_kernel<<<RESN * 2, OSN, SMEM_COL>>>(out);
}